// round 3
// baseline (speedup 1.0000x reference)
#include <cuda_runtime.h>
#include <cuda_bf16.h>
#include <cstdint>
#include <cstddef>

// Problem constants
#define BATCH   32
#define TSTEPS  2048
#define INDIM   256
#define HDIM    256
#define GDIM    768            // 3*H
#define OUTDIM  256

// Scratch for xg = x @ W_i + bias : (B*T, 3H) fp32 = 192 MB
__device__ float g_xg[(size_t)BATCH * TSTEPS * GDIM];

// ---------------------------------------------------------------------------
// Helpers
// ---------------------------------------------------------------------------
__device__ __forceinline__ uint32_t smem_u32(const void* p) {
    uint32_t a;
    asm("{ .reg .u64 t; cvta.to.shared.u64 t, %1; cvt.u32.u64 %0, t; }"
        : "=r"(a) : "l"(p));
    return a;
}

__device__ __forceinline__ void cluster_sync_() {
    asm volatile("barrier.cluster.arrive.aligned;" ::: "memory");
    asm volatile("barrier.cluster.wait.aligned;" ::: "memory");
}

// overflow-safe fast sigmoid / tanh (MUFU-only)
__device__ __forceinline__ float sigmoid_(float x) {
    float e = __expf(-x);                      // x<<0 -> inf -> 1/inf = 0  OK
    return __fdividef(1.0f, 1.0f + e);
}
__device__ __forceinline__ float tanh_(float x) {
    float e = __expf(2.0f * x);                // x<<0 -> 0 -> 1-2 = -1  OK
    return 1.0f - __fdividef(2.0f, e + 1.0f);  // x>>0 -> inf -> 1-0 = 1 OK
}

__device__ __forceinline__ void mbar_init_(uint32_t addr, uint32_t cnt) {
    asm volatile("mbarrier.init.shared.b64 [%0], %1;" :: "r"(addr), "r"(cnt) : "memory");
}
__device__ __forceinline__ void mbar_arrive_remote_(uint32_t addr) {
    asm volatile("mbarrier.arrive.release.cluster.shared::cluster.b64 _, [%0];"
                 :: "r"(addr) : "memory");
}
__device__ __forceinline__ void bar_wait_(uint32_t mbar, uint32_t parity) {
    uint32_t done;
    asm volatile("{\n\t.reg .pred p;\n\t"
                 "mbarrier.try_wait.parity.acquire.cluster.shared::cta.b64 p, [%1], %2;\n\t"
                 "selp.b32 %0, 1, 0, p;\n\t}"
                 : "=r"(done) : "r"(mbar), "r"(parity) : "memory");
    while (!done) {
        asm volatile("{\n\t.reg .pred p;\n\t"
                     "mbarrier.try_wait.parity.acquire.cluster.shared::cta.b64 p, [%1], %2, 0x989680;\n\t"
                     "selp.b32 %0, 1, 0, p;\n\t}"
                     : "=r"(done) : "r"(mbar), "r"(parity) : "memory");
    }
}

// ---------------------------------------------------------------------------
// Kernel 1: xg = x @ W_i + bias    (M=65536, N=768, K=256)  fp32 tiled SGEMM
// (unchanged from R1 — measured 677us)
// ---------------------------------------------------------------------------
__global__ __launch_bounds__(256)
void gemm_xg_kernel(const float* __restrict__ X,
                    const float* __restrict__ Wi,
                    const float* __restrict__ bias)
{
    __shared__ __align__(16) float As[16][128];   // transposed A tile
    __shared__ __align__(16) float Bs[16][64];

    const int bm = blockIdx.x * 128;
    const int bn = blockIdx.y * 64;
    const int tid = threadIdx.x;
    const int tx = tid & 15;       // N direction (4 cols each)
    const int ty = tid >> 4;       // M direction (8 rows each)

    float acc[8][4];
#pragma unroll
    for (int i = 0; i < 8; ++i)
#pragma unroll
        for (int j = 0; j < 4; ++j) acc[i][j] = 0.0f;

    for (int k0 = 0; k0 < INDIM; k0 += 16) {
#pragma unroll
        for (int q = 0; q < 2; ++q) {
            int f   = q * 256 + tid;
            int row = f >> 2;
            int k4  = (f & 3) << 2;
            float4 v = *reinterpret_cast<const float4*>(
                X + (size_t)(bm + row) * INDIM + k0 + k4);
            As[k4 + 0][row] = v.x;
            As[k4 + 1][row] = v.y;
            As[k4 + 2][row] = v.z;
            As[k4 + 3][row] = v.w;
        }
        {
            int kr = tid >> 4;
            int c4 = (tid & 15) << 2;
            float4 v = *reinterpret_cast<const float4*>(
                Wi + (size_t)(k0 + kr) * GDIM + bn + c4);
            *reinterpret_cast<float4*>(&Bs[kr][c4]) = v;
        }
        __syncthreads();

#pragma unroll
        for (int kk = 0; kk < 16; ++kk) {
            float4 a0 = *reinterpret_cast<const float4*>(&As[kk][ty * 8]);
            float4 a1 = *reinterpret_cast<const float4*>(&As[kk][ty * 8 + 4]);
            float4 bv = *reinterpret_cast<const float4*>(&Bs[kk][tx * 4]);
            float a[8] = {a0.x, a0.y, a0.z, a0.w, a1.x, a1.y, a1.z, a1.w};
            float bb[4] = {bv.x, bv.y, bv.z, bv.w};
#pragma unroll
            for (int i = 0; i < 8; ++i)
#pragma unroll
                for (int j = 0; j < 4; ++j)
                    acc[i][j] = fmaf(a[i], bb[j], acc[i][j]);
        }
        __syncthreads();
    }

    float4 bv = *reinterpret_cast<const float4*>(bias + bn + tx * 4);
#pragma unroll
    for (int i = 0; i < 8; ++i) {
        int row = bm + ty * 8 + i;
        float4 o;
        o.x = acc[i][0] + bv.x;
        o.y = acc[i][1] + bv.y;
        o.z = acc[i][2] + bv.z;
        o.w = acc[i][3] + bv.w;
        *reinterpret_cast<float4*>(g_xg + (size_t)row * GDIM + bn + tx * 4) = o;
    }
}

// ---------------------------------------------------------------------------
// Kernel 2: GRU recurrence.
// Grid = 128 CTAs, cluster of 4 per batch row, 256 threads/CTA.
// Thread (j, ks): j = tid>>2 in [0,64), ks = tid&3 in [0,4).
// Owns all 3 gate columns (r,z,n) of H-index crank*64+j over K slice
// [ks*64, ks*64+64); W_h held in 192 registers (rotated chunk order by 2*ks
// so the 4 K-slices hit disjoint smem bank groups).
// Per step: FFMA dots -> shfl_xor K-reduce -> ks==0 lane: gate math, state
// STGs, h broadcast via st.shared::cluster + remote mbarrier arrive (release)
// -> all threads try_wait (acquire). mbarrier phases auto-reset: no re-arm.
// ---------------------------------------------------------------------------
__global__ __launch_bounds__(256, 1) __cluster_dims__(4, 1, 1)
void gru_rec_kernel(const float* __restrict__ Wh,
                    float* __restrict__ states)
{
    __shared__ __align__(16) float h_sm[2][HDIM];
    __shared__ __align__(8) unsigned long long bars[2];

    uint32_t crank;
    asm("mov.u32 %0, %%cluster_ctarank;" : "=r"(crank));
    const int b   = blockIdx.x >> 2;
    const int tid = threadIdx.x;
    const int j   = tid >> 2;       // H index within this CTA's 64-chunk
    const int ks  = tid & 3;        // K slice
    const int colbase = (int)crank * 64 + j;   // gate g column = g*HDIM + colbase

    // ---- Load W_h into registers, chunk order rotated by 2*ks ----
    // chunk c (c=0..15) covers K = ks*64 + rho(c)*4 .. +3, rho(c)=(c+2*ks)&15
    float W0[64], W1[64], W2[64];
    {
#pragma unroll
        for (int c = 0; c < 16; ++c) {
            int rho = (c + 2 * ks) & 15;
            int kbase = ks * 64 + rho * 4;
#pragma unroll
            for (int e = 0; e < 4; ++e) {
                const float* wr = Wh + (size_t)(kbase + e) * GDIM;
                W0[c * 4 + e] = wr[colbase];
                W1[c * 4 + e] = wr[HDIM + colbase];
                W2[c * 4 + e] = wr[2 * HDIM + colbase];
            }
        }
    }

    // ---- Init shared state & barriers ----
    if (tid < HDIM) { h_sm[0][tid] = 0.0f; h_sm[1][tid] = 0.0f; }
    const uint32_t bar_l0 = smem_u32(&bars[0]);
    const uint32_t bar_l1 = smem_u32(&bars[1]);
    if (tid == 0) {
        mbar_init_(bar_l0, 256);   // 64 gate threads x 4 CTAs per phase
        mbar_init_(bar_l1, 256);
    }
    __syncthreads();
    cluster_sync_();   // zeros + barrier inits visible cluster-wide

    // ---- Remote addresses (dst h slot + barrier, per buffer, per rank) ----
    uint32_t dst_addr[2][4], bar_addr[2][4];
    {
        uint32_t l0 = smem_u32(&h_sm[0][colbase]);
        uint32_t l1 = smem_u32(&h_sm[1][colbase]);
#pragma unroll
        for (int rk = 0; rk < 4; ++rk) {
            asm("mapa.shared::cluster.u32 %0, %1, %2;" : "=r"(dst_addr[0][rk]) : "r"(l0), "r"(rk));
            asm("mapa.shared::cluster.u32 %0, %1, %2;" : "=r"(dst_addr[1][rk]) : "r"(l1), "r"(rk));
            asm("mapa.shared::cluster.u32 %0, %1, %2;" : "=r"(bar_addr[0][rk]) : "r"(bar_l0), "r"(rk));
            asm("mapa.shared::cluster.u32 %0, %1, %2;" : "=r"(bar_addr[1][rk]) : "r"(bar_l1), "r"(rk));
        }
    }

    // ---- xg pointer + first prefetch (gate lanes only) ----
    const float* xgp = g_xg + (size_t)b * TSTEPS * GDIM + colbase;
    float xr = 0.f, xz = 0.f, xn = 0.f;
    if (ks == 0) {
        xr = xgp[0];
        xz = xgp[HDIM];
        xn = xgp[2 * HDIM];
    }

    const size_t PL = (size_t)TSTEPS * HDIM;                 // plane stride
    float* sp0 = states + (size_t)b * 4 * PL + colbase;      // plane 0, t=0

    int ph0 = 0, ph1 = 0;
    const int koff = 2 * ks;  // chunk rotation

    for (int t = 0; t < TSTEPS; ++t) {
        const int cur = t & 1;
        const int nxt = cur ^ 1;

        // ---- 3 dots of length 64 (bank-conflict-free rotated reads) ----
        const float* hs = &h_sm[cur][ks * 64];
        float a0 = 0.f, a1 = 0.f, a2 = 0.f;
        float b0 = 0.f, b1 = 0.f, b2 = 0.f;
#pragma unroll
        for (int c = 0; c < 16; ++c) {
            int rho = (c + koff) & 15;
            float4 hv = *reinterpret_cast<const float4*>(hs + rho * 4);
            a0 = fmaf(W0[c * 4 + 0], hv.x, a0);
            a1 = fmaf(W1[c * 4 + 0], hv.x, a1);
            a2 = fmaf(W2[c * 4 + 0], hv.x, a2);
            b0 = fmaf(W0[c * 4 + 1], hv.y, b0);
            b1 = fmaf(W1[c * 4 + 1], hv.y, b1);
            b2 = fmaf(W2[c * 4 + 1], hv.y, b2);
            a0 = fmaf(W0[c * 4 + 2], hv.z, a0);
            a1 = fmaf(W1[c * 4 + 2], hv.z, a1);
            a2 = fmaf(W2[c * 4 + 2], hv.z, a2);
            b0 = fmaf(W0[c * 4 + 3], hv.w, b0);
            b1 = fmaf(W1[c * 4 + 3], hv.w, b1);
            b2 = fmaf(W2[c * 4 + 3], hv.w, b2);
        }
        float s0 = a0 + b0, s1 = a1 + b1, s2 = a2 + b2;
        // reduce across the 4 K-slices (lane bits 0-1)
        s0 += __shfl_xor_sync(0xffffffffu, s0, 1);
        s1 += __shfl_xor_sync(0xffffffffu, s1, 1);
        s2 += __shfl_xor_sync(0xffffffffu, s2, 1);
        s0 += __shfl_xor_sync(0xffffffffu, s0, 2);
        s1 += __shfl_xor_sync(0xffffffffu, s1, 2);
        s2 += __shfl_xor_sync(0xffffffffu, s2, 2);

        const bool last = (t == TSTEPS - 1);

        if (ks == 0) {
            float r  = sigmoid_(xr + s0);
            float z  = sigmoid_(xz + s1);
            float gg = xn + s2;
            float n  = tanh_(fmaf(r, gg, gg));          // tanh(gn + r*gn)
            float h_old = h_sm[cur][colbase];
            float hn = fmaf(z, h_old - n, n);           // (1-z)n + z h

            float* sp = sp0 + (size_t)t * HDIM;
            sp[0]      = hn;
            sp[PL]     = r;
            sp[2 * PL] = z;
            sp[3 * PL] = n;

            if (!last) {
                // h into next buffer of all 4 CTAs: store then release-arrive
#pragma unroll
                for (int rk = 0; rk < 4; ++rk) {
                    asm volatile("st.shared::cluster.f32 [%0], %1;"
                                 :: "r"(dst_addr[nxt][rk]), "f"(hn) : "memory");
                    mbar_arrive_remote_(bar_addr[nxt][rk]);
                }
                // prefetch next xg
                const float* xq = xgp + (size_t)(t + 1) * GDIM;
                xr = xq[0];
                xz = xq[HDIM];
                xn = xq[2 * HDIM];
            }
        }

        if (!last) {
            if (nxt) { bar_wait_(bar_l1, (uint32_t)ph1); ph1 ^= 1; }
            else     { bar_wait_(bar_l0, (uint32_t)ph0); ph0 ^= 1; }
        }
    }
}

// ---------------------------------------------------------------------------
// Kernel 3: output = h_last @ fc_w + fc_b   (32 x 256, K=256) — tiny
// ---------------------------------------------------------------------------
__global__ __launch_bounds__(256)
void fc_kernel(const float* __restrict__ states,
               const float* __restrict__ fc_w,
               const float* __restrict__ fc_b,
               float* __restrict__ out)
{
    const int b = blockIdx.x;
    const int o = threadIdx.x;
    const float* h = states + (((size_t)b * 4 + 0) * TSTEPS + (TSTEPS - 1)) * HDIM;
    float a0 = 0.f, a1 = 0.f, a2 = 0.f, a3 = 0.f;
#pragma unroll 8
    for (int k = 0; k < HDIM; k += 4) {
        a0 = fmaf(h[k + 0], fc_w[(size_t)(k + 0) * OUTDIM + o], a0);
        a1 = fmaf(h[k + 1], fc_w[(size_t)(k + 1) * OUTDIM + o], a1);
        a2 = fmaf(h[k + 2], fc_w[(size_t)(k + 2) * OUTDIM + o], a2);
        a3 = fmaf(h[k + 3], fc_w[(size_t)(k + 3) * OUTDIM + o], a3);
    }
    out[(size_t)b * OUTDIM + o] = (a0 + a1) + (a2 + a3) + fc_b[o];
}

// ---------------------------------------------------------------------------
// Launch
// ---------------------------------------------------------------------------
extern "C" void kernel_launch(void* const* d_in, const int* in_sizes, int n_in,
                              void* d_out, int out_size)
{
    const float* x    = (const float*)d_in[0];
    const float* Wi   = (const float*)d_in[1];
    const float* Wh   = (const float*)d_in[2];
    const float* bias = (const float*)d_in[3];
    const float* fcw  = (const float*)d_in[4];
    const float* fcb  = (const float*)d_in[5];

    float* out    = (float*)d_out;                 // (32, 256)
    float* states = out + (size_t)BATCH * OUTDIM;  // (32, 4, 2048, 256)

    dim3 ggrid((BATCH * TSTEPS) / 128, GDIM / 64);
    gemm_xg_kernel<<<ggrid, 256>>>(x, Wi, bias);

    gru_rec_kernel<<<BATCH * 4, 256>>>(Wh, states);

    fc_kernel<<<BATCH, 256>>>(states, fcw, fcb, out);
}

// round 4
// speedup vs baseline: 1.0509x; 1.0509x over previous
#include <cuda_runtime.h>
#include <cuda_bf16.h>
#include <cstdint>
#include <cstddef>

// Problem constants
#define BATCH   32
#define TSTEPS  2048
#define INDIM   256
#define HDIM    256
#define GDIM    768            // 3*H
#define OUTDIM  256

// Scratch for xg = x @ W_i + bias : (B*T, 3H) fp32 = 192 MB
__device__ float g_xg[(size_t)BATCH * TSTEPS * GDIM];

// ---------------------------------------------------------------------------
// Helpers
// ---------------------------------------------------------------------------
__device__ __forceinline__ uint32_t smem_u32(const void* p) {
    uint32_t a;
    asm("{ .reg .u64 t; cvta.to.shared.u64 t, %1; cvt.u32.u64 %0, t; }"
        : "=r"(a) : "l"(p));
    return a;
}

__device__ __forceinline__ void cluster_sync_() {
    asm volatile("barrier.cluster.arrive.aligned;" ::: "memory");
    asm volatile("barrier.cluster.wait.aligned;" ::: "memory");
}

// overflow-safe fast sigmoid / tanh (MUFU-only)
__device__ __forceinline__ float sigmoid_(float x) {
    float e = __expf(-x);
    return __fdividef(1.0f, 1.0f + e);
}
__device__ __forceinline__ float tanh_(float x) {
    float e = __expf(2.0f * x);
    return 1.0f - __fdividef(2.0f, e + 1.0f);
}

__device__ __forceinline__ void mbar_init_(uint32_t addr, uint32_t cnt) {
    asm volatile("mbarrier.init.shared.b64 [%0], %1;" :: "r"(addr), "r"(cnt) : "memory");
}
__device__ __forceinline__ void mbar_arrive_remote_(uint32_t addr) {
    asm volatile("mbarrier.arrive.release.cluster.shared::cluster.b64 _, [%0];"
                 :: "r"(addr) : "memory");
}
__device__ __forceinline__ void bar_wait_(uint32_t mbar, uint32_t parity) {
    uint32_t done;
    asm volatile("{\n\t.reg .pred p;\n\t"
                 "mbarrier.try_wait.parity.acquire.cluster.shared::cta.b64 p, [%1], %2;\n\t"
                 "selp.b32 %0, 1, 0, p;\n\t}"
                 : "=r"(done) : "r"(mbar), "r"(parity) : "memory");
    while (!done) {
        asm volatile("{\n\t.reg .pred p;\n\t"
                     "mbarrier.try_wait.parity.acquire.cluster.shared::cta.b64 p, [%1], %2, 0x989680;\n\t"
                     "selp.b32 %0, 1, 0, p;\n\t}"
                     : "=r"(done) : "r"(mbar), "r"(parity) : "memory");
    }
}

// ---------------------------------------------------------------------------
// Kernel 1: xg = x @ W_i + bias    (M=65536, N=768, K=256)  fp32 tiled SGEMM
// (unchanged — measured 677us; variable isolation this round)
// ---------------------------------------------------------------------------
__global__ __launch_bounds__(256)
void gemm_xg_kernel(const float* __restrict__ X,
                    const float* __restrict__ Wi,
                    const float* __restrict__ bias)
{
    __shared__ __align__(16) float As[16][128];   // transposed A tile
    __shared__ __align__(16) float Bs[16][64];

    const int bm = blockIdx.x * 128;
    const int bn = blockIdx.y * 64;
    const int tid = threadIdx.x;
    const int tx = tid & 15;       // N direction (4 cols each)
    const int ty = tid >> 4;       // M direction (8 rows each)

    float acc[8][4];
#pragma unroll
    for (int i = 0; i < 8; ++i)
#pragma unroll
        for (int j = 0; j < 4; ++j) acc[i][j] = 0.0f;

    for (int k0 = 0; k0 < INDIM; k0 += 16) {
#pragma unroll
        for (int q = 0; q < 2; ++q) {
            int f   = q * 256 + tid;
            int row = f >> 2;
            int k4  = (f & 3) << 2;
            float4 v = *reinterpret_cast<const float4*>(
                X + (size_t)(bm + row) * INDIM + k0 + k4);
            As[k4 + 0][row] = v.x;
            As[k4 + 1][row] = v.y;
            As[k4 + 2][row] = v.z;
            As[k4 + 3][row] = v.w;
        }
        {
            int kr = tid >> 4;
            int c4 = (tid & 15) << 2;
            float4 v = *reinterpret_cast<const float4*>(
                Wi + (size_t)(k0 + kr) * GDIM + bn + c4);
            *reinterpret_cast<float4*>(&Bs[kr][c4]) = v;
        }
        __syncthreads();

#pragma unroll
        for (int kk = 0; kk < 16; ++kk) {
            float4 a0 = *reinterpret_cast<const float4*>(&As[kk][ty * 8]);
            float4 a1 = *reinterpret_cast<const float4*>(&As[kk][ty * 8 + 4]);
            float4 bv = *reinterpret_cast<const float4*>(&Bs[kk][tx * 4]);
            float a[8] = {a0.x, a0.y, a0.z, a0.w, a1.x, a1.y, a1.z, a1.w};
            float bb[4] = {bv.x, bv.y, bv.z, bv.w};
#pragma unroll
            for (int i = 0; i < 8; ++i)
#pragma unroll
                for (int j = 0; j < 4; ++j)
                    acc[i][j] = fmaf(a[i], bb[j], acc[i][j]);
        }
        __syncthreads();
    }

    float4 bv = *reinterpret_cast<const float4*>(bias + bn + tx * 4);
#pragma unroll
    for (int i = 0; i < 8; ++i) {
        int row = bm + ty * 8 + i;
        float4 o;
        o.x = acc[i][0] + bv.x;
        o.y = acc[i][1] + bv.y;
        o.z = acc[i][2] + bv.z;
        o.w = acc[i][3] + bv.w;
        *reinterpret_cast<float4*>(g_xg + (size_t)row * GDIM + bn + tx * 4) = o;
    }
}

// ---------------------------------------------------------------------------
// Kernel 2: GRU recurrence.
// Grid = 128 CTAs, cluster of 4 per batch row, 256 threads/CTA.
// Thread (j, ks): j = tid>>2 in [0,64), ks = tid&3 in [0,4).
// Owns all 3 gate columns (r,z,n) of H-index crank*64+j over K slice
// [ks*64, +64); W_h in 192 registers, chunk order rotated by 2*ks for
// conflict-free LDS.
// Per step: FFMA dots -> shfl_xor K-reduce -> gate lanes: gate math +
// remote h stores -> __syncthreads -> tid0 releases 4 arrives (count=4
// barriers, aggregated: NO per-lane atomics) -> states STG + xg prefetch
// overlap peers -> try_wait.acquire.
// ---------------------------------------------------------------------------
__global__ __launch_bounds__(256, 1) __cluster_dims__(4, 1, 1)
void gru_rec_kernel(const float* __restrict__ Wh,
                    float* __restrict__ states)
{
    __shared__ __align__(16) float h_sm[2][HDIM];
    __shared__ __align__(8) unsigned long long bars[2];

    uint32_t crank;
    asm("mov.u32 %0, %%cluster_ctarank;" : "=r"(crank));
    const int b   = blockIdx.x >> 2;
    const int tid = threadIdx.x;
    const int j   = tid >> 2;       // H index within this CTA's 64-chunk
    const int ks  = tid & 3;        // K slice
    const int colbase = (int)crank * 64 + j;   // gate g column = g*HDIM + colbase

    // ---- Load W_h into registers, chunk order rotated by 2*ks ----
    float W0[64], W1[64], W2[64];
    {
#pragma unroll
        for (int c = 0; c < 16; ++c) {
            int rho = (c + 2 * ks) & 15;
            int kbase = ks * 64 + rho * 4;
#pragma unroll
            for (int e = 0; e < 4; ++e) {
                const float* wr = Wh + (size_t)(kbase + e) * GDIM;
                W0[c * 4 + e] = wr[colbase];
                W1[c * 4 + e] = wr[HDIM + colbase];
                W2[c * 4 + e] = wr[2 * HDIM + colbase];
            }
        }
    }

    // ---- Init shared state & barriers ----
    if (tid < HDIM) { h_sm[0][tid] = 0.0f; h_sm[1][tid] = 0.0f; }
    const uint32_t bar_l0 = smem_u32(&bars[0]);
    const uint32_t bar_l1 = smem_u32(&bars[1]);
    if (tid == 0) {
        mbar_init_(bar_l0, 4);   // ONE aggregated arrive per CTA per phase
        mbar_init_(bar_l1, 4);
    }
    __syncthreads();
    cluster_sync_();   // zeros + barrier inits visible cluster-wide

    // ---- Remote addresses ----
    uint32_t dst_addr[2][4];     // h slot in each rank, per buffer (gate lanes)
    uint32_t bar_addr[2][4];     // each rank's barrier, per buffer (tid0)
    {
        uint32_t l0 = smem_u32(&h_sm[0][colbase]);
        uint32_t l1 = smem_u32(&h_sm[1][colbase]);
#pragma unroll
        for (int rk = 0; rk < 4; ++rk) {
            asm("mapa.shared::cluster.u32 %0, %1, %2;" : "=r"(dst_addr[0][rk]) : "r"(l0), "r"(rk));
            asm("mapa.shared::cluster.u32 %0, %1, %2;" : "=r"(dst_addr[1][rk]) : "r"(l1), "r"(rk));
            asm("mapa.shared::cluster.u32 %0, %1, %2;" : "=r"(bar_addr[0][rk]) : "r"(bar_l0), "r"(rk));
            asm("mapa.shared::cluster.u32 %0, %1, %2;" : "=r"(bar_addr[1][rk]) : "r"(bar_l1), "r"(rk));
        }
    }

    // ---- xg pointer + first prefetch (gate lanes only) ----
    const float* xgp = g_xg + (size_t)b * TSTEPS * GDIM + colbase;
    float xr = 0.f, xz = 0.f, xn = 0.f;
    if (ks == 0) {
        xr = xgp[0];
        xz = xgp[HDIM];
        xn = xgp[2 * HDIM];
    }

    const size_t PL = (size_t)TSTEPS * HDIM;                 // plane stride
    float* sp0 = states + (size_t)b * 4 * PL + colbase;      // plane 0, t=0

    int ph0 = 0, ph1 = 0;
    const int koff = 2 * ks;

    for (int t = 0; t < TSTEPS; ++t) {
        const int cur = t & 1;
        const int nxt = cur ^ 1;

        // ---- 3 dots of length 64 (rotated conflict-free LDS reads) ----
        const float* hs = &h_sm[cur][ks * 64];
        float a0 = 0.f, a1 = 0.f, a2 = 0.f;
        float b0 = 0.f, b1 = 0.f, b2 = 0.f;
#pragma unroll
        for (int c = 0; c < 16; ++c) {
            int rho = (c + koff) & 15;
            float4 hv = *reinterpret_cast<const float4*>(hs + rho * 4);
            a0 = fmaf(W0[c * 4 + 0], hv.x, a0);
            a1 = fmaf(W1[c * 4 + 0], hv.x, a1);
            a2 = fmaf(W2[c * 4 + 0], hv.x, a2);
            b0 = fmaf(W0[c * 4 + 1], hv.y, b0);
            b1 = fmaf(W1[c * 4 + 1], hv.y, b1);
            b2 = fmaf(W2[c * 4 + 1], hv.y, b2);
            a0 = fmaf(W0[c * 4 + 2], hv.z, a0);
            a1 = fmaf(W1[c * 4 + 2], hv.z, a1);
            a2 = fmaf(W2[c * 4 + 2], hv.z, a2);
            b0 = fmaf(W0[c * 4 + 3], hv.w, b0);
            b1 = fmaf(W1[c * 4 + 3], hv.w, b1);
            b2 = fmaf(W2[c * 4 + 3], hv.w, b2);
        }
        float s0 = a0 + b0, s1 = a1 + b1, s2 = a2 + b2;
        s0 += __shfl_xor_sync(0xffffffffu, s0, 1);
        s1 += __shfl_xor_sync(0xffffffffu, s1, 1);
        s2 += __shfl_xor_sync(0xffffffffu, s2, 1);
        s0 += __shfl_xor_sync(0xffffffffu, s0, 2);
        s1 += __shfl_xor_sync(0xffffffffu, s1, 2);
        s2 += __shfl_xor_sync(0xffffffffu, s2, 2);

        const bool last = (t == TSTEPS - 1);

        float r = 0.f, z = 0.f, n = 0.f, hn = 0.f;
        if (ks == 0) {
            r  = sigmoid_(xr + s0);
            z  = sigmoid_(xz + s1);
            float gg = xn + s2;
            n  = tanh_(fmaf(r, gg, gg));                // tanh(gn + r*gn)
            float h_old = h_sm[cur][colbase];
            hn = fmaf(z, h_old - n, n);                 // (1-z)n + z h

            if (!last) {
                // push h chunk into next buffer of all 4 CTAs
#pragma unroll
                for (int rk = 0; rk < 4; ++rk) {
                    asm volatile("st.shared::cluster.f32 [%0], %1;"
                                 :: "r"(dst_addr[nxt][rk]), "f"(hn) : "memory");
                }
            }
        }

        if (!last) {
            __syncthreads();   // orders all gate lanes' DSMEM stores (BAR drains STS)
            if (tid == 0) {
                // single aggregated release-arrive to each CTA's barrier
#pragma unroll
                for (int rk = 0; rk < 4; ++rk) mbar_arrive_remote_(bar_addr[nxt][rk]);
            }
        }

        // ---- off-critical-path work: states STG + next xg prefetch ----
        if (ks == 0) {
            float* sp = sp0 + (size_t)t * HDIM;
            sp[0]      = hn;
            sp[PL]     = r;
            sp[2 * PL] = z;
            sp[3 * PL] = n;
            if (!last) {
                const float* xq = xgp + (size_t)(t + 1) * GDIM;
                xr = xq[0];
                xz = xq[HDIM];
                xn = xq[2 * HDIM];
            }
        }

        if (!last) {
            if (nxt) { bar_wait_(bar_l1, (uint32_t)ph1); ph1 ^= 1; }
            else     { bar_wait_(bar_l0, (uint32_t)ph0); ph0 ^= 1; }
        }
    }
}

// ---------------------------------------------------------------------------
// Kernel 3: output = h_last @ fc_w + fc_b   (32 x 256, K=256) — tiny
// ---------------------------------------------------------------------------
__global__ __launch_bounds__(256)
void fc_kernel(const float* __restrict__ states,
               const float* __restrict__ fc_w,
               const float* __restrict__ fc_b,
               float* __restrict__ out)
{
    const int b = blockIdx.x;
    const int o = threadIdx.x;
    const float* h = states + (((size_t)b * 4 + 0) * TSTEPS + (TSTEPS - 1)) * HDIM;
    float a0 = 0.f, a1 = 0.f, a2 = 0.f, a3 = 0.f;
#pragma unroll 8
    for (int k = 0; k < HDIM; k += 4) {
        a0 = fmaf(h[k + 0], fc_w[(size_t)(k + 0) * OUTDIM + o], a0);
        a1 = fmaf(h[k + 1], fc_w[(size_t)(k + 1) * OUTDIM + o], a1);
        a2 = fmaf(h[k + 2], fc_w[(size_t)(k + 2) * OUTDIM + o], a2);
        a3 = fmaf(h[k + 3], fc_w[(size_t)(k + 3) * OUTDIM + o], a3);
    }
    out[(size_t)b * OUTDIM + o] = (a0 + a1) + (a2 + a3) + fc_b[o];
}

// ---------------------------------------------------------------------------
// Launch
// ---------------------------------------------------------------------------
extern "C" void kernel_launch(void* const* d_in, const int* in_sizes, int n_in,
                              void* d_out, int out_size)
{
    const float* x    = (const float*)d_in[0];
    const float* Wi   = (const float*)d_in[1];
    const float* Wh   = (const float*)d_in[2];
    const float* bias = (const float*)d_in[3];
    const float* fcw  = (const float*)d_in[4];
    const float* fcb  = (const float*)d_in[5];

    float* out    = (float*)d_out;                 // (32, 256)
    float* states = out + (size_t)BATCH * OUTDIM;  // (32, 4, 2048, 256)

    dim3 ggrid((BATCH * TSTEPS) / 128, GDIM / 64);
    gemm_xg_kernel<<<ggrid, 256>>>(x, Wi, bias);

    gru_rec_kernel<<<BATCH * 4, 256>>>(Wh, states);

    fc_kernel<<<BATCH, 256>>>(states, fcw, fcb, out);
}

// round 5
// speedup vs baseline: 1.0935x; 1.0405x over previous
#include <cuda_runtime.h>
#include <cuda_bf16.h>
#include <cstdint>
#include <cstddef>

// Problem constants
#define BATCH   32
#define TSTEPS  2048
#define INDIM   256
#define HDIM    256
#define GDIM    768            // 3*H
#define OUTDIM  256

// Scratch for xg = x @ W_i + bias : (B*T, 3H) fp32 = 192 MB
__device__ float g_xg[(size_t)BATCH * TSTEPS * GDIM];

// ---------------------------------------------------------------------------
// Helpers
// ---------------------------------------------------------------------------
__device__ __forceinline__ uint32_t smem_u32(const void* p) {
    uint32_t a;
    asm("{ .reg .u64 t; cvta.to.shared.u64 t, %1; cvt.u32.u64 %0, t; }"
        : "=r"(a) : "l"(p));
    return a;
}

__device__ __forceinline__ void cluster_sync_() {
    asm volatile("barrier.cluster.arrive.aligned;" ::: "memory");
    asm volatile("barrier.cluster.wait.aligned;" ::: "memory");
}

// overflow-safe fast sigmoid / tanh (MUFU-only)
__device__ __forceinline__ float sigmoid_(float x) {
    float e = __expf(-x);
    return __fdividef(1.0f, 1.0f + e);
}
__device__ __forceinline__ float tanh_(float x) {
    float e = __expf(2.0f * x);
    return 1.0f - __fdividef(2.0f, e + 1.0f);
}

__device__ __forceinline__ void mbar_init_(uint32_t addr, uint32_t cnt) {
    asm volatile("mbarrier.init.shared.b64 [%0], %1;" :: "r"(addr), "r"(cnt) : "memory");
}
__device__ __forceinline__ void mbar_arrive_remote_(uint32_t addr) {
    asm volatile("mbarrier.arrive.release.cluster.shared::cluster.b64 _, [%0];"
                 :: "r"(addr) : "memory");
}
__device__ __forceinline__ void bar_wait_(uint32_t mbar, uint32_t parity) {
    uint32_t done;
    asm volatile("{\n\t.reg .pred p;\n\t"
                 "mbarrier.try_wait.parity.acquire.cluster.shared::cta.b64 p, [%1], %2;\n\t"
                 "selp.b32 %0, 1, 0, p;\n\t}"
                 : "=r"(done) : "r"(mbar), "r"(parity) : "memory");
    while (!done) {
        asm volatile("{\n\t.reg .pred p;\n\t"
                     "mbarrier.try_wait.parity.acquire.cluster.shared::cta.b64 p, [%1], %2, 0x989680;\n\t"
                     "selp.b32 %0, 1, 0, p;\n\t}"
                     : "=r"(done) : "r"(mbar), "r"(parity) : "memory");
    }
}

// ---------------------------------------------------------------------------
// Kernel 1: xg = x @ W_i + bias    (M=65536, N=768, K=256)  fp32 tiled SGEMM
// (unchanged — measured 676us; variable isolation this round)
// ---------------------------------------------------------------------------
__global__ __launch_bounds__(256)
void gemm_xg_kernel(const float* __restrict__ X,
                    const float* __restrict__ Wi,
                    const float* __restrict__ bias)
{
    __shared__ __align__(16) float As[16][128];   // transposed A tile
    __shared__ __align__(16) float Bs[16][64];

    const int bm = blockIdx.x * 128;
    const int bn = blockIdx.y * 64;
    const int tid = threadIdx.x;
    const int tx = tid & 15;       // N direction (4 cols each)
    const int ty = tid >> 4;       // M direction (8 rows each)

    float acc[8][4];
#pragma unroll
    for (int i = 0; i < 8; ++i)
#pragma unroll
        for (int j = 0; j < 4; ++j) acc[i][j] = 0.0f;

    for (int k0 = 0; k0 < INDIM; k0 += 16) {
#pragma unroll
        for (int q = 0; q < 2; ++q) {
            int f   = q * 256 + tid;
            int row = f >> 2;
            int k4  = (f & 3) << 2;
            float4 v = *reinterpret_cast<const float4*>(
                X + (size_t)(bm + row) * INDIM + k0 + k4);
            As[k4 + 0][row] = v.x;
            As[k4 + 1][row] = v.y;
            As[k4 + 2][row] = v.z;
            As[k4 + 3][row] = v.w;
        }
        {
            int kr = tid >> 4;
            int c4 = (tid & 15) << 2;
            float4 v = *reinterpret_cast<const float4*>(
                Wi + (size_t)(k0 + kr) * GDIM + bn + c4);
            *reinterpret_cast<float4*>(&Bs[kr][c4]) = v;
        }
        __syncthreads();

#pragma unroll
        for (int kk = 0; kk < 16; ++kk) {
            float4 a0 = *reinterpret_cast<const float4*>(&As[kk][ty * 8]);
            float4 a1 = *reinterpret_cast<const float4*>(&As[kk][ty * 8 + 4]);
            float4 bv = *reinterpret_cast<const float4*>(&Bs[kk][tx * 4]);
            float a[8] = {a0.x, a0.y, a0.z, a0.w, a1.x, a1.y, a1.z, a1.w};
            float bb[4] = {bv.x, bv.y, bv.z, bv.w};
#pragma unroll
            for (int i = 0; i < 8; ++i)
#pragma unroll
                for (int j = 0; j < 4; ++j)
                    acc[i][j] = fmaf(a[i], bb[j], acc[i][j]);
        }
        __syncthreads();
    }

    float4 bv = *reinterpret_cast<const float4*>(bias + bn + tx * 4);
#pragma unroll
    for (int i = 0; i < 8; ++i) {
        int row = bm + ty * 8 + i;
        float4 o;
        o.x = acc[i][0] + bv.x;
        o.y = acc[i][1] + bv.y;
        o.z = acc[i][2] + bv.z;
        o.w = acc[i][3] + bv.w;
        *reinterpret_cast<float4*>(g_xg + (size_t)row * GDIM + bn + tx * 4) = o;
    }
}

// ---------------------------------------------------------------------------
// Kernel 2: GRU recurrence.
// Grid = 128 CTAs, cluster of 4 per batch row, 256 threads/CTA.
// Thread (j, ks): j = tid>>2, ks = tid&3. Owns 3 gate columns of H-index
// crank*64+j over K slice [ks*64,+64); W_h in 192 registers (rotated by 2*ks
// for conflict-free LDS).
// Per step: FFMA dots -> shfl K-reduce -> gate lanes: gate math + LOCAL h
// store (no remote STS before BAR!) -> __syncthreads (cheap local drain) ->
// pusher lanes 1/2/3 each copy the 64-float chunk to ONE remote rank via
// 32x st.shared::cluster.b64 + release-arrive on that rank's barrier; lane 5
// arrives locally. States STG + xg prefetch overlap transit -> try_wait.
// ---------------------------------------------------------------------------
__global__ __launch_bounds__(256, 1) __cluster_dims__(4, 1, 1)
void gru_rec_kernel(const float* __restrict__ Wh,
                    float* __restrict__ states)
{
    __shared__ __align__(16) float h_sm[2][HDIM];
    __shared__ __align__(8) unsigned long long bars[2];

    uint32_t crank;
    asm("mov.u32 %0, %%cluster_ctarank;" : "=r"(crank));
    const int b   = blockIdx.x >> 2;
    const int tid = threadIdx.x;
    const int j   = tid >> 2;       // H index within this CTA's 64-chunk
    const int ks  = tid & 3;        // K slice
    const int colbase = (int)crank * 64 + j;

    // ---- Load W_h into registers, chunk order rotated by 2*ks ----
    float W0[64], W1[64], W2[64];
    {
#pragma unroll
        for (int c = 0; c < 16; ++c) {
            int rho = (c + 2 * ks) & 15;
            int kbase = ks * 64 + rho * 4;
#pragma unroll
            for (int e = 0; e < 4; ++e) {
                const float* wr = Wh + (size_t)(kbase + e) * GDIM;
                W0[c * 4 + e] = wr[colbase];
                W1[c * 4 + e] = wr[HDIM + colbase];
                W2[c * 4 + e] = wr[2 * HDIM + colbase];
            }
        }
    }

    // ---- Init shared state & barriers ----
    if (tid < HDIM) { h_sm[0][tid] = 0.0f; h_sm[1][tid] = 0.0f; }
    const uint32_t bar_l0 = smem_u32(&bars[0]);
    const uint32_t bar_l1 = smem_u32(&bars[1]);
    if (tid == 0) {
        mbar_init_(bar_l0, 4);   // 1 local + 3 remote aggregated arrives/phase
        mbar_init_(bar_l1, 4);
    }
    __syncthreads();
    cluster_sync_();   // zeros + barrier inits visible cluster-wide

    // ---- Pusher precompute: lane 1/2/3 -> remote rank (crank+tid)&3 ----
    // push_dst[p]: remote h_sm[p] slot for MY chunk in that rank's smem.
    // push_bar[p]: that rank's barrier p.
    uint32_t push_dst[2], push_bar[2];
    {
        uint32_t rk = (crank + (uint32_t)tid) & 3u;   // meaningful for tid 1..3
        uint32_t l0 = smem_u32(&h_sm[0][0]);
        uint32_t l1 = smem_u32(&h_sm[1][0]);
        uint32_t r0, r1, rb0, rb1;
        asm("mapa.shared::cluster.u32 %0, %1, %2;" : "=r"(r0)  : "r"(l0),    "r"(rk));
        asm("mapa.shared::cluster.u32 %0, %1, %2;" : "=r"(r1)  : "r"(l1),    "r"(rk));
        asm("mapa.shared::cluster.u32 %0, %1, %2;" : "=r"(rb0) : "r"(bar_l0), "r"(rk));
        asm("mapa.shared::cluster.u32 %0, %1, %2;" : "=r"(rb1) : "r"(bar_l1), "r"(rk));
        push_dst[0] = r0 + crank * 64u * 4u;
        push_dst[1] = r1 + crank * 64u * 4u;
        push_bar[0] = rb0;
        push_bar[1] = rb1;
    }

    // ---- xg pointer + first prefetch (gate lanes only) ----
    const float* xgp = g_xg + (size_t)b * TSTEPS * GDIM + colbase;
    float xr = 0.f, xz = 0.f, xn = 0.f;
    if (ks == 0) {
        xr = xgp[0];
        xz = xgp[HDIM];
        xn = xgp[2 * HDIM];
    }

    const size_t PL = (size_t)TSTEPS * HDIM;                 // plane stride
    float* sp0 = states + (size_t)b * 4 * PL + colbase;      // plane 0, t=0

    int ph0 = 0, ph1 = 0;
    const int koff = 2 * ks;

    for (int t = 0; t < TSTEPS; ++t) {
        const int cur = t & 1;
        const int nxt = cur ^ 1;

        // ---- 3 dots of length 64 (rotated conflict-free LDS reads) ----
        const float* hs = &h_sm[cur][ks * 64];
        float a0 = 0.f, a1 = 0.f, a2 = 0.f;
        float b0 = 0.f, b1 = 0.f, b2 = 0.f;
#pragma unroll
        for (int c = 0; c < 16; ++c) {
            int rho = (c + koff) & 15;
            float4 hv = *reinterpret_cast<const float4*>(hs + rho * 4);
            a0 = fmaf(W0[c * 4 + 0], hv.x, a0);
            a1 = fmaf(W1[c * 4 + 0], hv.x, a1);
            a2 = fmaf(W2[c * 4 + 0], hv.x, a2);
            b0 = fmaf(W0[c * 4 + 1], hv.y, b0);
            b1 = fmaf(W1[c * 4 + 1], hv.y, b1);
            b2 = fmaf(W2[c * 4 + 1], hv.y, b2);
            a0 = fmaf(W0[c * 4 + 2], hv.z, a0);
            a1 = fmaf(W1[c * 4 + 2], hv.z, a1);
            a2 = fmaf(W2[c * 4 + 2], hv.z, a2);
            b0 = fmaf(W0[c * 4 + 3], hv.w, b0);
            b1 = fmaf(W1[c * 4 + 3], hv.w, b1);
            b2 = fmaf(W2[c * 4 + 3], hv.w, b2);
        }
        float s0 = a0 + b0, s1 = a1 + b1, s2 = a2 + b2;
        s0 += __shfl_xor_sync(0xffffffffu, s0, 1);
        s1 += __shfl_xor_sync(0xffffffffu, s1, 1);
        s2 += __shfl_xor_sync(0xffffffffu, s2, 1);
        s0 += __shfl_xor_sync(0xffffffffu, s0, 2);
        s1 += __shfl_xor_sync(0xffffffffu, s1, 2);
        s2 += __shfl_xor_sync(0xffffffffu, s2, 2);

        const bool last = (t == TSTEPS - 1);

        float r = 0.f, z = 0.f, n = 0.f, hn = 0.f;
        if (ks == 0) {
            r  = sigmoid_(xr + s0);
            z  = sigmoid_(xz + s1);
            float gg = xn + s2;
            n  = tanh_(fmaf(r, gg, gg));                // tanh(gn + r*gn)
            float h_old = h_sm[cur][colbase];
            hn = fmaf(z, h_old - n, n);                 // (1-z)n + z h
            // LOCAL store only — keeps the upcoming BAR drain cheap
            h_sm[nxt][colbase] = hn;
        }

        if (!last) {
            __syncthreads();   // local STS drain only (fast)

            if (tid >= 1 && tid <= 3) {
                // push my CTA's 64-float chunk to ONE remote rank (b64 x32),
                // then release-arrive: orders this thread's stores.
                const unsigned long long* src =
                    reinterpret_cast<const unsigned long long*>(&h_sm[nxt][(int)crank * 64]);
                const uint32_t dst = push_dst[nxt];
#pragma unroll
                for (int i = 0; i < 32; ++i) {
                    unsigned long long v = src[i];
                    asm volatile("st.shared::cluster.b64 [%0], %1;"
                                 :: "r"(dst + (uint32_t)i * 8u), "l"(v) : "memory");
                }
                mbar_arrive_remote_(push_bar[nxt]);
            } else if (tid == 5) {
                // local arrive (visibility already via BAR)
                mbar_arrive_remote_(nxt ? bar_l1 : bar_l0);
            }
        }

        // ---- off-critical-path: states STG + next xg prefetch ----
        if (ks == 0) {
            float* sp = sp0 + (size_t)t * HDIM;
            sp[0]      = hn;
            sp[PL]     = r;
            sp[2 * PL] = z;
            sp[3 * PL] = n;
            if (!last) {
                const float* xq = xgp + (size_t)(t + 1) * GDIM;
                xr = xq[0];
                xz = xq[HDIM];
                xn = xq[2 * HDIM];
            }
        }

        if (!last) {
            if (nxt) { bar_wait_(bar_l1, (uint32_t)ph1); ph1 ^= 1; }
            else     { bar_wait_(bar_l0, (uint32_t)ph0); ph0 ^= 1; }
        }
    }
}

// ---------------------------------------------------------------------------
// Kernel 3: output = h_last @ fc_w + fc_b   (32 x 256, K=256) — tiny
// ---------------------------------------------------------------------------
__global__ __launch_bounds__(256)
void fc_kernel(const float* __restrict__ states,
               const float* __restrict__ fc_w,
               const float* __restrict__ fc_b,
               float* __restrict__ out)
{
    const int b = blockIdx.x;
    const int o = threadIdx.x;
    const float* h = states + (((size_t)b * 4 + 0) * TSTEPS + (TSTEPS - 1)) * HDIM;
    float a0 = 0.f, a1 = 0.f, a2 = 0.f, a3 = 0.f;
#pragma unroll 8
    for (int k = 0; k < HDIM; k += 4) {
        a0 = fmaf(h[k + 0], fc_w[(size_t)(k + 0) * OUTDIM + o], a0);
        a1 = fmaf(h[k + 1], fc_w[(size_t)(k + 1) * OUTDIM + o], a1);
        a2 = fmaf(h[k + 2], fc_w[(size_t)(k + 2) * OUTDIM + o], a2);
        a3 = fmaf(h[k + 3], fc_w[(size_t)(k + 3) * OUTDIM + o], a3);
    }
    out[(size_t)b * OUTDIM + o] = (a0 + a1) + (a2 + a3) + fc_b[o];
}

// ---------------------------------------------------------------------------
// Launch
// ---------------------------------------------------------------------------
extern "C" void kernel_launch(void* const* d_in, const int* in_sizes, int n_in,
                              void* d_out, int out_size)
{
    const float* x    = (const float*)d_in[0];
    const float* Wi   = (const float*)d_in[1];
    const float* Wh   = (const float*)d_in[2];
    const float* bias = (const float*)d_in[3];
    const float* fcw  = (const float*)d_in[4];
    const float* fcb  = (const float*)d_in[5];

    float* out    = (float*)d_out;                 // (32, 256)
    float* states = out + (size_t)BATCH * OUTDIM;  // (32, 4, 2048, 256)

    dim3 ggrid((BATCH * TSTEPS) / 128, GDIM / 64);
    gemm_xg_kernel<<<ggrid, 256>>>(x, Wi, bias);

    gru_rec_kernel<<<BATCH * 4, 256>>>(Wh, states);

    fc_kernel<<<BATCH, 256>>>(states, fcw, fcb, out);
}